// round 9
// baseline (speedup 1.0000x reference)
#include <cuda_runtime.h>
#include <cuda_bf16.h>
#include <cstdint>

// Problem constants
#define D_FULL   8192
#define K_NNZ    1024
#define NTHREADS 256
#define SMEM_WORDS (D_FULL + (D_FULL >> 5))   // pad 1 word per 32 -> 8448
#define SCALE_F  0.011048543456039806f        // 1/sqrt(8192)

// padded physical index: one pad word every 32 floats (bank-conflict-free in all passes)
__device__ __forceinline__ int P(int i) { return i + (i >> 5); }

__device__ __forceinline__ void radix32(float v[32]) {
#pragma unroll
    for (int h = 1; h < 32; h <<= 1) {
#pragma unroll
        for (int i = 0; i < 32; i++) {
            if ((i & h) == 0) {
                float a = v[i];
                float b = v[i + h];
                v[i]     = a + b;
                v[i + h] = a - b;
            }
        }
    }
}

__global__ void __launch_bounds__(NTHREADS)
fwht_kernel(const float* __restrict__ u,
            const int*   __restrict__ idx,
            float*       __restrict__ out)
{
    __shared__ float z[SMEM_WORDS];
    const int t   = threadIdx.x;
    const int l   = t & 31;
    const int w   = t >> 5;
    const int row = blockIdx.x;

    // ---- Phase 0: zero smem ----
#pragma unroll
    for (int i = t; i < SMEM_WORDS; i += NTHREADS)
        z[i] = 0.0f;
    __syncthreads();

    // ---- Phase 1: scatter. idx is SORTED, so duplicates are adjacent runs.
    // An element whose index differs from both sorted neighbors is the only
    // writer of its slot -> plain STS. Only duplicate-run members use atomics.
    {
        const int4   id = reinterpret_cast<const int4*>(idx)[t];
        const float4 uu = reinterpret_cast<const float4*>(u + (size_t)row * K_NNZ)[t];
        const int prev = (t > 0)            ? idx[4 * t - 1] : -1;
        const int nxt  = (t < NTHREADS - 1) ? idx[4 * t + 4] : -1;

        if (id.x != prev && id.x != id.y) z[P(id.x)] = uu.x; else atomicAdd(&z[P(id.x)], uu.x);
        if (id.y != id.x && id.y != id.z) z[P(id.y)] = uu.y; else atomicAdd(&z[P(id.y)], uu.y);
        if (id.z != id.y && id.z != id.w) z[P(id.z)] = uu.z; else atomicAdd(&z[P(id.z)], uu.z);
        if (id.w != id.z && id.w != nxt)  z[P(id.w)] = uu.w; else atomicAdd(&z[P(id.w)], uu.w);
    }
    __syncthreads();

    float v[32];

    // ---- Pass A: elem bits 4..2 (radix-8). Thread owns contiguous [32t, 32t+32).
    // Physical addresses 33t + a are contiguous; bank = (t + a) mod 32 -> conflict-free.
    {
        const int pb = t * 33;
#pragma unroll
        for (int a = 0; a < 32; a++) v[a] = z[pb + a];
#pragma unroll
        for (int h = 4; h < 32; h <<= 1) {
#pragma unroll
            for (int a = 0; a < 32; a++) {
                if ((a & h) == 0) {
                    float x = v[a], y = v[a + h];
                    v[a] = x + y; v[a + h] = x - y;
                }
            }
        }
#pragma unroll
        for (int a = 0; a < 32; a++) z[pb + a] = v[a];
    }
    __syncthreads();

    // ---- Pass B: elem bits 9..5 (radix-32).
    // elem = l + 32a + 1024w  ->  phys = l + 33a + 1056w ; bank = (l + a) mod 32 -> conflict-free.
    {
        const int pb = l + 1056 * w;
#pragma unroll
        for (int a = 0; a < 32; a++) v[a] = z[pb + 33 * a];
        radix32(v);
#pragma unroll
        for (int a = 0; a < 32; a++) z[pb + 33 * a] = v[a];
    }
    __syncthreads();

    // ---- Pass C: elem bits 1..0 and 12..10 together (radix-32 over a = i + 4j).
    // elem = i + 4l + 128w + 1024j  ->  phys = i + 4l + (l>>3) + 132w + 1056j
    // bank = (i + 4(l&7) + (l>>3) + ...) mod 32 -> lane-distinct, conflict-free.
    // Final ownership makes STG.128 perfectly coalesced: per instr, lanes write
    // 32 consecutive float4s (512B contiguous = 4 wavefronts, the minimum).
    {
        const int pb = 4 * l + (l >> 3) + 132 * w;
#pragma unroll
        for (int j = 0; j < 8; j++) {
#pragma unroll
            for (int i = 0; i < 4; i++)
                v[4 * j + i] = z[pb + 1056 * j + i];
        }
        radix32(v);   // a-bits 0,1 = elem bits 1,0 ; a-bits 2,3,4 = elem bits 10,11,12

        float* orow = out + (size_t)row * D_FULL + 4 * l + 128 * w;
#pragma unroll
        for (int j = 0; j < 8; j++) {
            float4 st;
            st.x = v[4 * j + 0] * SCALE_F;
            st.y = v[4 * j + 1] * SCALE_F;
            st.z = v[4 * j + 2] * SCALE_F;
            st.w = v[4 * j + 3] * SCALE_F;
            reinterpret_cast<float4*>(orow + 1024 * j)[0] = st;
        }
    }
}

extern "C" void kernel_launch(void* const* d_in, const int* in_sizes, int n_in,
                              void* d_out, int out_size)
{
    const float* u   = (const float*)d_in[0];   // (4, 2048, 1024) fp32
    const int*   idx = (const int*)d_in[1];     // (1024,) int32, sorted
    float*       out = (float*)d_out;           // (4, 2048, 8192) fp32

    const int rows = in_sizes[0] / K_NNZ;       // 8192
    fwht_kernel<<<rows, NTHREADS>>>(u, idx, out);
}

// round 14
// speedup vs baseline: 1.7964x; 1.7964x over previous
#include <cuda_runtime.h>
#include <cuda_bf16.h>
#include <cstdint>

#define D_FULL   8192
#define K_NNZ    1024
#define NTHREADS 256
#define SMEM_F2  4478                         // max of psi2 image + 1
#define SCALE_F  0.011048543456039806f        // 1/sqrt(8192)

union F2U { float2 f; unsigned long long u; };

// (a,b) -> (a+b, a-b), both components packed. Sub via fma(b,-1,a) (exact).
__device__ __forceinline__ void bfly2(float2& a, float2& b, unsigned long long neg1) {
    F2U x, y, s, d;
    x.f = a; y.f = b;
    asm("add.rn.f32x2 %0, %1, %2;" : "=l"(s.u) : "l"(x.u), "l"(y.u));
    asm("fma.rn.f32x2 %0, %1, %2, %3;" : "=l"(d.u) : "l"(y.u), "l"(neg1), "l"(x.u));
    a = s.f; b = d.f;
}

__device__ __forceinline__ float2 pmul2(float2 a, unsigned long long sc) {
    F2U x, r; x.f = a;
    asm("mul.rn.f32x2 %0, %1, %2;" : "=l"(r.u) : "l"(x.u), "l"(sc));
    return r.f;
}

// radix-16 butterfly network over the 4 in-thread j-bits (packed over float2)
__device__ __forceinline__ void radix16(float2 v[16], unsigned long long neg1) {
#pragma unroll
    for (int h = 1; h < 16; h <<= 1) {
#pragma unroll
        for (int i = 0; i < 16; i++) {
            if ((i & h) == 0) bfly2(v[i], v[i + h], neg1);
        }
    }
}

__global__ void __launch_bounds__(NTHREADS, 4)
fwht_kernel(const float* __restrict__ u,
            const int*   __restrict__ idx,
            float*       __restrict__ out)
{
    // float2 element j holds output/input elems (2j, 2j+1). j in [0,4096).
    // Stage layouts (bijective paddings, chosen per writer/reader pair):
    //   psi0(j) = j                      scatter -> A   (A load: lane-contiguous)
    //   psi1(j) = j + (j>>5)             A -> B         (store stride1, load stride33: ok)
    //   psi2(j) = j + (j>>4) + (j>>5)    B -> C         (store stride35, load stride2+(l>>3): ok)
    // Passes transform IN PLACE between different layouts, so each pass has a
    // barrier between its register-load phase and its store phase (values sit
    // in registers across the barrier). Without it, a fast warp's psi_{k+1}
    // stores can overwrite psi_k slots a slow warp hasn't read yet.
    __shared__ __align__(16) float2 Z[SMEM_F2];
    float*  zf = reinterpret_cast<float*>(Z);
    float4* z4 = reinterpret_cast<float4*>(Z);

    const int t   = threadIdx.x;
    const int l   = t & 31;
    const int w   = t >> 5;
    const int row = blockIdx.x;

    F2U negu; negu.f = make_float2(-1.0f, -1.0f);
    F2U scu;  scu.f  = make_float2(SCALE_F, SCALE_F);
    const unsigned long long NEG1 = negu.u;
    const unsigned long long SC2  = scu.u;

    // ---- zero the psi0 region: 4096 float2 = 2048 float4, 8 per thread ----
#pragma unroll
    for (int i = 0; i < 8; i++)
        z4[t + 256 * i] = make_float4(0.f, 0.f, 0.f, 0.f);
    __syncthreads();

    // ---- scatter (identity layout: float index == elem index). idx sorted;
    //      plain store unless a sorted neighbor matches (then atomic). ----
    {
        const int4   id = reinterpret_cast<const int4*>(idx)[t];
        const float4 uu = reinterpret_cast<const float4*>(u + (size_t)row * K_NNZ)[t];
        const int prev = (t > 0)            ? idx[4 * t - 1] : -1;
        const int nxt  = (t < NTHREADS - 1) ? idx[4 * t + 4] : -1;

        if (id.x != prev && id.x != id.y) zf[id.x] = uu.x; else atomicAdd(&zf[id.x], uu.x);
        if (id.y != id.x && id.y != id.z) zf[id.y] = uu.y; else atomicAdd(&zf[id.y], uu.y);
        if (id.z != id.y && id.z != id.w) zf[id.z] = uu.z; else atomicAdd(&zf[id.z], uu.z);
        if (id.w != id.z && id.w != nxt)  zf[id.w] = uu.w; else atomicAdd(&zf[id.w], uu.w);
    }
    __syncthreads();

    float2 v[16];

    // ---- Pass A: j = l + 32T + 512w. Butterflies j-bits {8..5} (=T). ----
    {
        const float2* src = Z + (l + 512 * w);            // psi0: lane-contiguous
#pragma unroll
        for (int T = 0; T < 16; T++) v[T] = src[32 * T];

        radix16(v, NEG1);

        __syncthreads();   // all psi0 reads done before any psi1 write

        float2* dst = Z + (l + 528 * w);                  // psi1: phys = l + 33T + 528w
#pragma unroll
        for (int T = 0; T < 16; T++) dst[33 * T] = v[T];
    }
    __syncthreads();

    // ---- Pass B: j = (w&1) + 2T + 32l + 1024(w>>1). Butterflies j-bits {4..1} (=T). ----
    {
        const float2* src = Z + ((w & 1) + 33 * l + 1056 * (w >> 1));   // psi1
#pragma unroll
        for (int T = 0; T < 16; T++) v[T] = src[2 * T];

        radix16(v, NEG1);

        __syncthreads();   // all psi1 reads done before any psi2 write

        float2* dst = Z + ((w & 1) + 35 * l + 1120 * (w >> 1));         // psi2
#pragma unroll
        for (int T = 0; T < 16; T++) dst[2 * T + (T >> 3)] = v[T];
    }
    __syncthreads();

    // ---- Pass C: j = (T&1) + 2l + 64w + 512(T>>1).
    //      Butterflies j-bits {0} (h=1) and {9,10,11} (h=2,4,8) = radix16 over T,
    //      then the intra-float2 stage (elem bit 0) + scale, then coalesced STG. ----
    {
        const float2* src = Z + (2 * l + (l >> 3) + (l >> 4) + 70 * w); // psi2
#pragma unroll
        for (int T = 0; T < 16; T++) v[T] = src[(T & 1) + 560 * (T >> 1)];

        radix16(v, NEG1);

        // scale first (commutes with the last butterfly), packed
#pragma unroll
        for (int T = 0; T < 16; T++) v[T] = pmul2(v[T], SC2);

        // out elem e = c + 2j = c + 2(T&1) + 4l + 128w + 1024(T>>1)
        // float4 index = l + 32w + 256s for s = T>>1; lanes contiguous -> coalesced
        float4* o4 = reinterpret_cast<float4*>(out) + ((size_t)row * (D_FULL / 4) + l + 32 * w);
#pragma unroll
        for (int s = 0; s < 8; s++) {
            float2 a = v[2 * s];
            float2 b = v[2 * s + 1];
            float4 st;
            st.x = a.x + a.y;   // e%4==0 : c-stage sum  (j even)
            st.y = a.x - a.y;   // e%4==1 : c-stage diff (j even)
            st.z = b.x + b.y;   // e%4==2 : j odd
            st.w = b.x - b.y;   // e%4==3
            o4[256 * s] = st;
        }
    }
}

extern "C" void kernel_launch(void* const* d_in, const int* in_sizes, int n_in,
                              void* d_out, int out_size)
{
    const float* u   = (const float*)d_in[0];   // (4, 2048, 1024) fp32
    const int*   idx = (const int*)d_in[1];     // (1024,) int32, sorted
    float*       out = (float*)d_out;           // (4, 2048, 8192) fp32

    const int rows = in_sizes[0] / K_NNZ;       // 8192
    fwht_kernel<<<rows, NTHREADS>>>(u, idx, out);
}